// round 15
// baseline (speedup 1.0000x reference)
#include <cuda_runtime.h>
#include <math.h>

// AFM layer: B=2048, F=50, E=64, A=10, P=1225.
// out[b] = sum_p softmax(l)_p * q_p.
// One block per batch element; 352 threads; each thread owns a 2x2 (i,j) Gram
// tile (4 pairs). f32x2 packed FMA.
// Weight operands split across ports: (w01,w23) via one broadcast LDS.128 per
// e-row, (w45,w67,w89,(p,p)) via const port as pre-packed u64s. Bias pairs
// fold into the accumulator init. Tile LUT computed inline. One gather kernel
// + one symbol memcpy stages all params (3 graph nodes total).

#define NF 50
#define NE 64
#define NA 10
#define NPAIR 1225
#define NTILE 325
#define THREADS 352
#define EPITCH 68           // dwords; conflict-free LDS.128
#define ZROW 25

typedef unsigned long long u64;

// ---- parameter block: filled by gather kernel, copied to constant ----
struct Params {
    ulonglong4 cc[NE];    // per e: (w4,w5)(w6,w7)(w8,w9)(p,p)
    float4 w0123[NE];     // per e: w0,w1,w2,w3  (staged to smem by afm blocks)
    float bp[NA];         // bias (pair-aligned)
    float h[NA];
};
__device__ __align__(16) Params g_stage;
__constant__ Params cPar;

#define STAGE_FLOATS (sizeof(Params) / 4)   // 512 + 256 + 10 + 10 = 788

__global__ void gather_params_kernel(const float* __restrict__ W,
                                     const float* __restrict__ bvec,
                                     const float* __restrict__ hvec,
                                     const float* __restrict__ pvec)
{
    int idx = blockIdx.x * blockDim.x + threadIdx.x;
    if (idx >= (int)STAGE_FLOATS) return;
    float v;
    if (idx < 512) {                    // cc: e*8 + {w4..w9, p, p}
        int e = idx >> 3, c = idx & 7;
        v = (c < 6) ? W[e * NA + 4 + c] : pvec[e];
    } else if (idx < 768) {             // w0123: e*4 + {w0..w3}
        int k = idx - 512;
        v = W[(k >> 2) * NA + (k & 3)];
    } else if (idx < 768 + NA) {
        v = bvec[idx - 768];
    } else {
        v = hvec[idx - 768 - NA];
    }
    reinterpret_cast<float*>(&g_stage)[idx] = v;
}

__device__ __forceinline__ u64 f2_mul(u64 a, u64 b) {
    u64 d; asm("mul.rn.f32x2 %0, %1, %2;" : "=l"(d) : "l"(a), "l"(b)); return d;
}
__device__ __forceinline__ u64 f2_fma(u64 a, u64 b, u64 c) {
    u64 d; asm("fma.rn.f32x2 %0, %1, %2, %3;" : "=l"(d) : "l"(a), "l"(b), "l"(c)); return d;
}
__device__ __forceinline__ u64 f2_pack(float lo, float hi) {
    u64 d; asm("mov.b64 %0, {%1, %2};" : "=l"(d) : "f"(lo), "f"(hi)); return d;
}
__device__ __forceinline__ u64 f2_bcast(float v) {
    u64 d; asm("mov.b64 %0, {%1, %1};" : "=l"(d) : "f"(v)); return d;
}
__device__ __forceinline__ void f2_unpack(u64 v, float& lo, float& hi) {
    asm("mov.b64 {%0, %1}, %2;" : "=f"(lo), "=f"(hi) : "l"(v));
}

__global__ __launch_bounds__(THREADS, 2)
void afm_kernel(const float* __restrict__ x, float* __restrict__ out)
{
    __shared__ __align__(16) float xev[(ZROW + 1) * EPITCH];
    __shared__ __align__(16) float xod[(ZROW + 1) * EPITCH];
    __shared__ __align__(16) float Wsh[NE * 4];   // per e: w0,w1,w2,w3
    __shared__ float red[11];
    __shared__ float red2[11];
    __shared__ float bcast;

    const int tid  = threadIdx.x;
    const int lane = tid & 31;
    const int wid  = tid >> 5;
    const int b    = blockIdx.x;

    // ---- load x[b] split into even/odd row arrays ----
    const float* xb = x + (size_t)b * (NF * NE);
    for (int idx = tid; idx < NF * NE; idx += THREADS) {
        int r = idx >> 6;
        int c = idx & 63;
        float v = xb[idx];
        if (r & 1) xod[(r >> 1) * EPITCH + c] = v;
        else       xev[(r >> 1) * EPITCH + c] = v;
    }
    for (int c = tid; c < EPITCH; c += THREADS) {
        xev[ZROW * EPITCH + c] = 0.0f;
        xod[ZROW * EPITCH + c] = 0.0f;
    }
    // stage w0..w3 rows into smem (from constant, once per block)
    if (tid < NE) {
        reinterpret_cast<float4*>(Wsh)[tid] = cPar.w0123[tid];
    }

    // ---- inline tile LUT: thread -> (bi, bj, mask) ----
    int bi = 0, bj = ZROW, mask = 0;
    if (tid < NTILE) {
        int rem = tid;
        while (rem >= 25 - bi) { rem -= 25 - bi; ++bi; }
        bj = bi + rem;
        mask = (bi < bj) ? 0xF : 0x2;    // diagonal tile: only (2bi, 2bi+1)
    } else {
        bi = ZROW;
    }
    const int bio = bi * EPITCH;
    const int bjo = bj * EPITCH;
    __syncthreads();

    // ---- bias pairs (constant); fold into acc init ----
    u64 bpair[5];
#pragma unroll
    for (int k = 0; k < 5; ++k)
        bpair[k] = *reinterpret_cast<const u64*>(cPar.bp + 2 * k);

    // pairs: 0=(ie,je) 1=(ie,jo) 2=(io,je) 3=(io,jo); acc lanes = W cols (2k,2k+1)
    u64 acc[4][5];
#pragma unroll
    for (int p = 0; p < 4; ++p)
#pragma unroll
        for (int k = 0; k < 5; ++k) acc[p][k] = bpair[k];
    u64 qacc01 = 0ull, qacc23 = 0ull;   // lanes (q_p0,q_p1), (q_p2,q_p3)

#pragma unroll 1
    for (int ec = 0; ec < NE; ec += 4) {
        ulonglong2 Xie = *reinterpret_cast<const ulonglong2*>(xev + bio + ec);
        ulonglong2 Xio = *reinterpret_cast<const ulonglong2*>(xod + bio + ec);
        ulonglong2 Xje = *reinterpret_cast<const ulonglong2*>(xev + bjo + ec);
        ulonglong2 Xjo = *reinterpret_cast<const ulonglong2*>(xod + bjo + ec);
        float ie[4], io[4], je[4], jo[4];
        f2_unpack(Xie.x, ie[0], ie[1]); f2_unpack(Xie.y, ie[2], ie[3]);
        f2_unpack(Xio.x, io[0], io[1]); f2_unpack(Xio.y, io[2], io[3]);
        f2_unpack(Xje.x, je[0], je[1]); f2_unpack(Xje.y, je[2], je[3]);
        f2_unpack(Xjo.x, jo[0], jo[1]); f2_unpack(Xjo.y, jo[2], jo[3]);

#pragma unroll
        for (int h = 0; h < 4; ++h) {
            // w0..w3 from smem (broadcast LDS.128)
            ulonglong2 wl =
                *reinterpret_cast<const ulonglong2*>(Wsh + (ec + h) * 4);
            u64 w0 = wl.x, w1 = wl.y;
            // w4..w9 and (p,p) from the const port (pre-packed)
            const u64* ccp = reinterpret_cast<const u64*>(&cPar.cc[ec + h]);
            u64 w2 = ccp[0], w3 = ccp[1], w4 = ccp[2];
            u64 wq = ccp[3];                         // (p_e, p_e)

            u64 jp  = f2_pack(je[h], jo[h]);
            u64 m01 = f2_mul(f2_bcast(ie[h]), jp);   // (pr_p0, pr_p1)
            u64 m23 = f2_mul(f2_bcast(io[h]), jp);   // (pr_p2, pr_p3)

            qacc01 = f2_fma(m01, wq, qacc01);
            qacc23 = f2_fma(m23, wq, qacc23);

            float p0, p1, p2, p3;
            f2_unpack(m01, p0, p1);
            f2_unpack(m23, p2, p3);
            u64 br0 = f2_bcast(p0), br1 = f2_bcast(p1);
            u64 br2 = f2_bcast(p2), br3 = f2_bcast(p3);

            acc[0][0] = f2_fma(br0, w0, acc[0][0]);
            acc[0][1] = f2_fma(br0, w1, acc[0][1]);
            acc[0][2] = f2_fma(br0, w2, acc[0][2]);
            acc[0][3] = f2_fma(br0, w3, acc[0][3]);
            acc[0][4] = f2_fma(br0, w4, acc[0][4]);
            acc[1][0] = f2_fma(br1, w0, acc[1][0]);
            acc[1][1] = f2_fma(br1, w1, acc[1][1]);
            acc[1][2] = f2_fma(br1, w2, acc[1][2]);
            acc[1][3] = f2_fma(br1, w3, acc[1][3]);
            acc[1][4] = f2_fma(br1, w4, acc[1][4]);
            acc[2][0] = f2_fma(br2, w0, acc[2][0]);
            acc[2][1] = f2_fma(br2, w1, acc[2][1]);
            acc[2][2] = f2_fma(br2, w2, acc[2][2]);
            acc[2][3] = f2_fma(br2, w3, acc[2][3]);
            acc[2][4] = f2_fma(br2, w4, acc[2][4]);
            acc[3][0] = f2_fma(br3, w0, acc[3][0]);
            acc[3][1] = f2_fma(br3, w1, acc[3][1]);
            acc[3][2] = f2_fma(br3, w2, acc[3][2]);
            acc[3][3] = f2_fma(br3, w3, acc[3][3]);
            acc[3][4] = f2_fma(br3, w4, acc[3][4]);
        }
    }

    // ---- logits + q (bias already folded into acc init) ----
    float qsc[4];
    f2_unpack(qacc01, qsc[0], qsc[1]);
    f2_unpack(qacc23, qsc[2], qsc[3]);

    float logit[4];
#pragma unroll
    for (int p = 0; p < 4; ++p) {
        float l = 0.0f;
#pragma unroll
        for (int k = 0; k < 5; ++k) {
            float a0, a1;
            f2_unpack(acc[p][k], a0, a1);
            a0 = a0 > 0.0f ? a0 : 0.0f;
            a1 = a1 > 0.0f ? a1 : 0.0f;
            l = fmaf(cPar.h[2 * k], a0, l);
            l = fmaf(cPar.h[2 * k + 1], a1, l);
        }
        logit[p] = (mask >> p) & 1 ? l : -INFINITY;
    }

    // ---- softmax-weighted scalar reduction ----
    float m = fmaxf(fmaxf(logit[0], logit[1]), fmaxf(logit[2], logit[3]));
#pragma unroll
    for (int o = 16; o > 0; o >>= 1)
        m = fmaxf(m, __shfl_xor_sync(0xFFFFFFFFu, m, o));
    if (lane == 0) red[wid] = m;
    __syncthreads();
    if (tid == 0) {
        float mm = red[0];
#pragma unroll
        for (int w = 1; w < THREADS / 32; ++w) mm = fmaxf(mm, red[w]);
        bcast = mm;
    }
    __syncthreads();
    const float mAll = bcast;

    float s = 0.0f, sq = 0.0f;
#pragma unroll
    for (int p = 0; p < 4; ++p) {
        float e = expf(logit[p] - mAll);
        s += e;
        sq = fmaf(e, qsc[p], sq);
    }
#pragma unroll
    for (int o = 16; o > 0; o >>= 1) {
        s  += __shfl_xor_sync(0xFFFFFFFFu, s, o);
        sq += __shfl_xor_sync(0xFFFFFFFFu, sq, o);
    }
    if (lane == 0) { red[wid] = s; red2[wid] = sq; }
    __syncthreads();
    if (tid == 0) {
        float ss = 0.0f, ssq = 0.0f;
#pragma unroll
        for (int w = 0; w < THREADS / 32; ++w) { ss += red[w]; ssq += red2[w]; }
        out[b] = ssq / ss;
    }
}

extern "C" void kernel_launch(void* const* d_in, const int* in_sizes, int n_in,
                              void* d_out, int out_size)
{
    const float* x = (const float*)d_in[0];   // [B, 50, 64]
    const float* W = (const float*)d_in[1];   // [64, 10]
    const float* b = (const float*)d_in[2];   // [10]
    const float* h = (const float*)d_in[3];   // [10, 1]
    const float* p = (const float*)d_in[4];   // [64, 1]
    float* out = (float*)d_out;               // [B, 1]

    int B = in_sizes[0] / (NF * NE);

    // 1) gather all params into one device staging struct
    gather_params_kernel<<<(STAGE_FLOATS + 255) / 256, 256>>>(W, b, h, p);

    // 2) one D2D symbol copy staging -> constant (graph-capturable)
    void* stage_ptr = nullptr;
    cudaGetSymbolAddress(&stage_ptr, g_stage);
    cudaMemcpyToSymbolAsync(cPar, stage_ptr, sizeof(Params), 0,
                            cudaMemcpyDeviceToDevice, 0);

    // 3) main kernel
    afm_kernel<<<B, THREADS>>>(x, out);
}

// round 17
// speedup vs baseline: 1.2494x; 1.2494x over previous
#include <cuda_runtime.h>
#include <math.h>

// AFM layer: B=2048, F=50, E=64, A=10, P=1225.
// out[b] = sum_p softmax(l)_p * q_p.
// One block per batch element; 352 threads; each thread owns a 2x2 (i,j) Gram
// tile (4 pairs). f32x2 packed FMA with PAIRS-IN-LANES accumulators:
//   acc01[k] = (pair0, pair1) partial sums of W column k, acc23 = (pair2,pair3)
// so the multiplier m01=(pr0,pr1) feeds FMAs directly (no unpack/bcast chain).
// Weights lane-duplicated in __constant__ (const port, LDC.128). x stored
// interleaved (even,odd) so (je,jo) is one LDS.64-in-128 load.

#define NF 50
#define NE 64
#define NA 10
#define NPAIR 1225
#define NTILE 325
#define THREADS 352
#define XPITCH 132          // dwords per r-row; 132 mod 32 = 4 -> conflict-free LDS.128
#define ZROW 25

typedef unsigned long long u64;

// ---- constant parameter block ----
struct Params {
    ulonglong2 wd[NE][6]; // per e: (w0,w0)(w1,w1) | (w2,w2)(w3,w3) | ... | (p,p)(p,p)
    u64 bd[NA];           // (b_k, b_k)
    float h[NA];
};
__device__ __align__(16) Params g_stage;
__constant__ Params cPar;

#define STAGE_FLOATS ((int)(sizeof(Params) / 4))   // 1536 + 20 + 10 = 1566

__global__ void gather_params_kernel(const float* __restrict__ W,
                                     const float* __restrict__ bvec,
                                     const float* __restrict__ hvec,
                                     const float* __restrict__ pvec)
{
    int idx = blockIdx.x * blockDim.x + threadIdx.x;
    if (idx >= STAGE_FLOATS) return;
    float v;
    if (idx < NE * 24) {                 // wd: e*24 floats; float f -> w_{f/2} or p
        int e = idx / 24, f = idx % 24;
        int k = f >> 1;
        v = (k < NA) ? W[e * NA + k] : pvec[e];
    } else if (idx < NE * 24 + 2 * NA) { // bd: (b_k, b_k)
        int f = idx - NE * 24;
        v = bvec[f >> 1];
    } else {                             // h
        v = hvec[idx - NE * 24 - 2 * NA];
    }
    reinterpret_cast<float*>(&g_stage)[idx] = v;
}

__device__ __forceinline__ u64 f2_mul(u64 a, u64 b) {
    u64 d; asm("mul.rn.f32x2 %0, %1, %2;" : "=l"(d) : "l"(a), "l"(b)); return d;
}
__device__ __forceinline__ u64 f2_fma(u64 a, u64 b, u64 c) {
    u64 d; asm("fma.rn.f32x2 %0, %1, %2, %3;" : "=l"(d) : "l"(a), "l"(b), "l"(c)); return d;
}
__device__ __forceinline__ u64 f2_bcast(float v) {
    u64 d; asm("mov.b64 %0, {%1, %1};" : "=l"(d) : "f"(v)); return d;
}
__device__ __forceinline__ void f2_unpack(u64 v, float& lo, float& hi) {
    asm("mov.b64 {%0, %1}, %2;" : "=f"(lo), "=f"(hi) : "l"(v));
}

__global__ __launch_bounds__(THREADS, 2)
void afm_kernel(const float* __restrict__ x, float* __restrict__ out)
{
    __shared__ __align__(16) float xint[(ZROW + 1) * XPITCH];  // interleaved (even,odd)
    __shared__ float red[11];
    __shared__ float red2[11];
    __shared__ float bcast;

    const int tid  = threadIdx.x;
    const int lane = tid & 31;
    const int wid  = tid >> 5;
    const int b    = blockIdx.x;

    // ---- load x[b] into interleaved layout: xint[r>>1][2c + (r&1)] ----
    const float* xb = x + (size_t)b * (NF * NE);
    for (int idx = tid; idx < NF * NE; idx += THREADS) {
        int r = idx >> 6;
        int c = idx & 63;
        xint[(r >> 1) * XPITCH + 2 * c + (r & 1)] = xb[idx];
    }
    for (int c = tid; c < XPITCH; c += THREADS)
        xint[ZROW * XPITCH + c] = 0.0f;

    // ---- inline tile LUT: thread -> (bi, bj, mask) ----
    int bi = 0, bj = ZROW, mask = 0;
    if (tid < NTILE) {
        int rem = tid;
        while (rem >= 25 - bi) { rem -= 25 - bi; ++bi; }
        bj = bi + rem;
        mask = (bi < bj) ? 0xF : 0x2;   // diag tile: only pair1 = (2bi, 2bi+1)
    } else {
        bi = ZROW;
    }
    const int bio = bi * XPITCH;
    const int bjo = bj * XPITCH;
    __syncthreads();

    // ---- accumulators: lanes = (pair0, pair1) / (pair2, pair3); bias folded ----
    u64 acc01[NA], acc23[NA];
#pragma unroll
    for (int k = 0; k < NA; ++k) {
        u64 bk = cPar.bd[k];
        acc01[k] = bk;
        acc23[k] = bk;
    }
    u64 qacc01 = 0ull, qacc23 = 0ull;

#pragma unroll 1
    for (int ec = 0; ec < NE; ec += 4) {
        // i-side: (ie,io) u64 per e; j-side: (je,jo) u64 per e == jp directly
        ulonglong2 Ia = *reinterpret_cast<const ulonglong2*>(xint + bio + 2 * ec);
        ulonglong2 Ib = *reinterpret_cast<const ulonglong2*>(xint + bio + 2 * ec + 4);
        ulonglong2 Ja = *reinterpret_cast<const ulonglong2*>(xint + bjo + 2 * ec);
        ulonglong2 Jb = *reinterpret_cast<const ulonglong2*>(xint + bjo + 2 * ec + 4);
        u64 jp[4] = { Ja.x, Ja.y, Jb.x, Jb.y };
        float ie[4], io[4];
        f2_unpack(Ia.x, ie[0], io[0]);
        f2_unpack(Ia.y, ie[1], io[1]);
        f2_unpack(Ib.x, ie[2], io[2]);
        f2_unpack(Ib.y, ie[3], io[3]);

#pragma unroll
        for (int h = 0; h < 4; ++h) {
            const ulonglong2* cw = cPar.wd[ec + h];   // 6 LDC.128
            ulonglong2 c0 = cw[0], c1 = cw[1], c2 = cw[2];
            ulonglong2 c3 = cw[3], c4 = cw[4], c5 = cw[5];

            u64 m01 = f2_mul(f2_bcast(ie[h]), jp[h]); // (pr_p0, pr_p1)
            u64 m23 = f2_mul(f2_bcast(io[h]), jp[h]); // (pr_p2, pr_p3)

            qacc01 = f2_fma(m01, c5.x, qacc01);       // (p_e, p_e)
            qacc23 = f2_fma(m23, c5.x, qacc23);

            acc01[0] = f2_fma(m01, c0.x, acc01[0]);
            acc01[1] = f2_fma(m01, c0.y, acc01[1]);
            acc01[2] = f2_fma(m01, c1.x, acc01[2]);
            acc01[3] = f2_fma(m01, c1.y, acc01[3]);
            acc01[4] = f2_fma(m01, c2.x, acc01[4]);
            acc01[5] = f2_fma(m01, c2.y, acc01[5]);
            acc01[6] = f2_fma(m01, c3.x, acc01[6]);
            acc01[7] = f2_fma(m01, c3.y, acc01[7]);
            acc01[8] = f2_fma(m01, c4.x, acc01[8]);
            acc01[9] = f2_fma(m01, c4.y, acc01[9]);
            acc23[0] = f2_fma(m23, c0.x, acc23[0]);
            acc23[1] = f2_fma(m23, c0.y, acc23[1]);
            acc23[2] = f2_fma(m23, c1.x, acc23[2]);
            acc23[3] = f2_fma(m23, c1.y, acc23[3]);
            acc23[4] = f2_fma(m23, c2.x, acc23[4]);
            acc23[5] = f2_fma(m23, c2.y, acc23[5]);
            acc23[6] = f2_fma(m23, c3.x, acc23[6]);
            acc23[7] = f2_fma(m23, c3.y, acc23[7]);
            acc23[8] = f2_fma(m23, c4.x, acc23[8]);
            acc23[9] = f2_fma(m23, c4.y, acc23[9]);
        }
    }

    // ---- logits + q (bias already in acc) ----
    float qsc[4];
    f2_unpack(qacc01, qsc[0], qsc[1]);
    f2_unpack(qacc23, qsc[2], qsc[3]);

    float l0 = 0.0f, l1 = 0.0f, l2 = 0.0f, l3 = 0.0f;
#pragma unroll
    for (int k = 0; k < NA; ++k) {
        float hk = cPar.h[k];
        float a0, a1, a2, a3;
        f2_unpack(acc01[k], a0, a1);
        f2_unpack(acc23[k], a2, a3);
        a0 = a0 > 0.0f ? a0 : 0.0f;
        a1 = a1 > 0.0f ? a1 : 0.0f;
        a2 = a2 > 0.0f ? a2 : 0.0f;
        a3 = a3 > 0.0f ? a3 : 0.0f;
        l0 = fmaf(hk, a0, l0);
        l1 = fmaf(hk, a1, l1);
        l2 = fmaf(hk, a2, l2);
        l3 = fmaf(hk, a3, l3);
    }
    float logit[4];
    logit[0] = (mask & 1) ? l0 : -INFINITY;
    logit[1] = (mask & 2) ? l1 : -INFINITY;
    logit[2] = (mask & 4) ? l2 : -INFINITY;
    logit[3] = (mask & 8) ? l3 : -INFINITY;

    // ---- softmax-weighted scalar reduction ----
    float m = fmaxf(fmaxf(logit[0], logit[1]), fmaxf(logit[2], logit[3]));
#pragma unroll
    for (int o = 16; o > 0; o >>= 1)
        m = fmaxf(m, __shfl_xor_sync(0xFFFFFFFFu, m, o));
    if (lane == 0) red[wid] = m;
    __syncthreads();
    if (tid == 0) {
        float mm = red[0];
#pragma unroll
        for (int w = 1; w < THREADS / 32; ++w) mm = fmaxf(mm, red[w]);
        bcast = mm;
    }
    __syncthreads();
    const float mAll = bcast;

    float s = 0.0f, sq = 0.0f;
#pragma unroll
    for (int p = 0; p < 4; ++p) {
        float e = expf(logit[p] - mAll);
        s += e;
        sq = fmaf(e, qsc[p], sq);
    }
#pragma unroll
    for (int o = 16; o > 0; o >>= 1) {
        s  += __shfl_xor_sync(0xFFFFFFFFu, s, o);
        sq += __shfl_xor_sync(0xFFFFFFFFu, sq, o);
    }
    if (lane == 0) { red[wid] = s; red2[wid] = sq; }
    __syncthreads();
    if (tid == 0) {
        float ss = 0.0f, ssq = 0.0f;
#pragma unroll
        for (int w = 0; w < THREADS / 32; ++w) { ss += red[w]; ssq += red2[w]; }
        out[b] = ssq / ss;
    }
}

extern "C" void kernel_launch(void* const* d_in, const int* in_sizes, int n_in,
                              void* d_out, int out_size)
{
    const float* x = (const float*)d_in[0];   // [B, 50, 64]
    const float* W = (const float*)d_in[1];   // [64, 10]
    const float* b = (const float*)d_in[2];   // [10]
    const float* h = (const float*)d_in[3];   // [10, 1]
    const float* p = (const float*)d_in[4];   // [64, 1]
    float* out = (float*)d_out;               // [B, 1]

    int B = in_sizes[0] / (NF * NE);

    gather_params_kernel<<<(STAGE_FLOATS + 255) / 256, 256>>>(W, b, h, p);

    void* stage_ptr = nullptr;
    cudaGetSymbolAddress(&stage_ptr, g_stage);
    cudaMemcpyToSymbolAsync(cPar, stage_ptr, sizeof(Params), 0,
                            cudaMemcpyDeviceToDevice, 0);

    afm_kernel<<<B, THREADS>>>(x, out);
}